// round 12
// baseline (speedup 1.0000x reference)
#include <cuda_runtime.h>

// AverageSpanExtractor: out[b,n,:] = mean(seq[b, start:end, :]) * mask[b,n]
// seq: [B,S,D] f32; spans: [B,N,2] i32; mask: [B,N] i32; out: [B,N,D] f32.
//
// G=8 consecutive spans per CTA (grid 1024 = single wave; no wave-transition
// tax). Lanes 0..7 load all 8 spans' metadata in one coalesced burst; the
// per-span loop gets (start,end,mask) via shfl -- zero serial metadata
// stalls between spans. Inner loop = proven R3 body (unroll-4 float4).

#define MAX_W 20
#define DIM   512
#define D4    (DIM / 4)
#define G     8

__global__ __launch_bounds__(128, 10)
void avg_span_kernel(const float* __restrict__ seq,
                     const int* __restrict__ spans,
                     const int* __restrict__ mask,
                     float* __restrict__ out,
                     int S, int N)
{
    const int t    = threadIdx.x;        // 0..127, owns float4 column t
    const int lane = t & 31;

    const int base = blockIdx.x * G;     // first span id of this CTA
    const int b    = base / N;           // G | N, so same batch for all G

    // one coalesced metadata burst per warp (lanes 0..G-1)
    int s_l = 0, e_l = 0, m_l = 0;
    if (lane < G) {
        const int2 se = ((const int2*)spans)[base + lane];
        s_l = se.x; e_l = se.y;
        m_l = mask[base + lane];
    }

    const float4* __restrict__ seqb = (const float4*)seq + (long long)b * S * D4;
    float4* __restrict__ outb = (float4*)out + (long long)base * D4 + t;

    #pragma unroll
    for (int i = 0; i < G; ++i) {
        const int s = __shfl_sync(0xffffffffu, s_l, i);
        const int e = __shfl_sync(0xffffffffu, e_l, i);
        const int m = __shfl_sync(0xffffffffu, m_l, i);

        int cnt = e - s;                         // width in [1, 20]
        cnt = (cnt < MAX_W) ? cnt : MAX_W;       // reference's static clamp
        cnt = (cnt > 0) ? cnt : 1;

        const float4* p = seqb + (long long)s * D4 + t;
        float4 acc = make_float4(0.f, 0.f, 0.f, 0.f);

        #pragma unroll 4
        for (int r = 0; r < cnt; ++r) {
            float4 v = *p;
            p += D4;
            acc.x += v.x; acc.y += v.y; acc.z += v.z; acc.w += v.w;
        }

        const float scale = (float)m / (float)cnt;
        acc.x *= scale; acc.y *= scale; acc.z *= scale; acc.w *= scale;

        outb[(long long)i * D4] = acc;
    }
}

extern "C" void kernel_launch(void* const* d_in, const int* in_sizes, int n_in,
                              void* d_out, int out_size)
{
    const float* seq  = (const float*)d_in[0];
    const int* spans  = (const int*)d_in[1];
    const int* mask   = (const int*)d_in[2];
    float* out        = (float*)d_out;

    const int DIMc = 512;
    const int S = 2048;
    const int B = in_sizes[0] / (S * DIMc);      // 8
    const int N = in_sizes[2] / B;               // 1024
    const int total = B * N;                     // 8192

    dim3 grid(total / G);                        // 1024 CTAs: single wave
    avg_span_kernel<<<grid, 128>>>(seq, spans, mask, out, S, N);
}